// round 3
// baseline (speedup 1.0000x reference)
#include <cuda_runtime.h>
#include <math.h>

#define KSEL   20
#define CAP    2048
#define M_OUT  180
#define ROWB   (M_OUT * 8)
#define BATCH  64
#define NF4_L0 8192   // 32768/4
#define NF4_L1 1024   // 4096/4
#define NF4_L2 128    // 512/4
#define NF4_TOT (NF4_L0 + NF4_L1 + NF4_L2)   // 9344

__device__ int   g_cnt[BATCH];
__device__ int   g_cntl[BATCH][3];
__device__ float g_v[BATCH * CAP];
__device__ int   g_key[BATCH * CAP];

__device__ __forceinline__ bool better(float va, int ka, float vb, int kb) {
    return (va > vb) || (va == vb && ka < kb);
}

// ---------------- Kernel A: reset counters + static -1 fill (rows 20..179) ----------------
__global__ __launch_bounds__(256)
void init_kernel(float* __restrict__ out) {
    const int b = blockIdx.x;
    if (threadIdx.x == 0) {
        g_cnt[b] = 0;
        g_cntl[b][0] = 0; g_cntl[b][1] = 0; g_cntl[b][2] = 0;
    }
    float4* o = (float4*)(out + (size_t)b * ROWB + KSEL * 8);
    const float4 neg = make_float4(-1.f, -1.f, -1.f, -1.f);
    for (int e = threadIdx.x; e < (M_OUT - KSEL) * 2; e += 256)
        o[e] = neg;
}

// ---------------- Kernel B: full-chip threshold scan ----------------
__global__ __launch_bounds__(256)
void scan_kernel(const float* __restrict__ cls0,
                 const float* __restrict__ cls1,
                 const float* __restrict__ cls2) {
    const int b = blockIdx.y;
    const int nthr = gridDim.x * blockDim.x;               // 8*256 = 2048
    int i4 = blockIdx.x * blockDim.x + threadIdx.x;

    const float4* p0 = (const float4*)(cls0 + (size_t)b * 32768);
    const float4* p1 = (const float4*)(cls1 + (size_t)b * 4096);
    const float4* p2 = (const float4*)(cls2 + (size_t)b * 512);

    for (; i4 < NF4_TOT; i4 += nthr) {
        int l, li4; const float4* p; float T;
        if (i4 < NF4_L0)              { l = 0; li4 = i4;                  p = p0; T = 2.5f; }
        else if (i4 < NF4_L0+NF4_L1)  { l = 1; li4 = i4 - NF4_L0;         p = p1; T = 1.9f; }
        else                          { l = 2; li4 = i4 - NF4_L0-NF4_L1;  p = p2; T = 1.0f; }
        float4 v = p[li4];
        float vv[4] = {v.x, v.y, v.z, v.w};
        #pragma unroll
        for (int c = 0; c < 4; c++) {
            if (vv[c] > T) {
                atomicAdd(&g_cntl[b][l], 1);
                int pos = atomicAdd(&g_cnt[b], 1);
                if (pos < CAP) {
                    g_v[b * CAP + pos]   = vv[c];
                    g_key[b * CAP + pos] = (l << 16) | (li4 * 4 + c);
                }
            }
        }
    }
}

// ---------------- Kernel C: select top-20, NMS, output ----------------
__global__ __launch_bounds__(128)
void select_kernel(const float* __restrict__ cls0, const float* __restrict__ shp0, const float* __restrict__ off0,
                   const float* __restrict__ cls1, const float* __restrict__ shp1, const float* __restrict__ off1,
                   const float* __restrict__ cls2, const float* __restrict__ shp2, const float* __restrict__ off2,
                   float* __restrict__ out)
{
    const int b    = blockIdx.x;
    const int tid  = threadIdx.x;
    const int nthr = blockDim.x;

    __shared__ float s_v[CAP];
    __shared__ int   s_key[CAP];
    __shared__ int   s_cnt;
    __shared__ int   s_cntl[3];
    __shared__ float sel_s[KSEL];
    __shared__ int   sel_key[KSEL];
    __shared__ float s_box[KSEL][6];
    __shared__ float s_score[KSEL];
    __shared__ int   s_valid[KSEL];
    __shared__ float s_iou[KSEL * KSEL];
    __shared__ int   s_rowof[KSEL];
    __shared__ int   s_count;

    int cnt  = g_cnt[b];
    int c0 = g_cntl[b][0], c1 = g_cntl[b][1], c2 = g_cntl[b][2];
    bool hot = (cnt <= CAP) && (c0 >= KSEL) && (c1 >= KSEL) && (c2 >= KSEL);

    int total;
    if (hot) {
        total = cnt;
        for (int i = tid; i < total; i += nthr) {
            s_v[i]   = g_v[b * CAP + i];
            s_key[i] = g_key[b * CAP + i];
        }
        __syncthreads();
    } else {
        // Cold fallback: in-block rescan with adaptive thresholds (exactness guard).
        const float* clsp[3] = {cls0, cls1, cls2};
        const int    Ns[3]   = {32768, 4096, 512};
        float T[3] = {2.5f, 1.9f, 1.0f};
        for (int attempt = 0; attempt < 32; attempt++) {
            if (tid == 0) { s_cnt = 0; s_cntl[0] = 0; s_cntl[1] = 0; s_cntl[2] = 0; }
            __syncthreads();
            #pragma unroll
            for (int l = 0; l < 3; l++) {
                const int N = Ns[l];
                const float4* p = (const float4*)(clsp[l] + (size_t)b * N);
                const float Tl = T[l];
                for (int i4 = tid; i4 < (N >> 2); i4 += nthr) {
                    float4 v = p[i4];
                    float vv[4] = {v.x, v.y, v.z, v.w};
                    #pragma unroll
                    for (int c = 0; c < 4; c++) {
                        if (vv[c] > Tl) {
                            atomicAdd(&s_cntl[l], 1);
                            int pos = atomicAdd(&s_cnt, 1);
                            if (pos < CAP) { s_v[pos] = vv[c]; s_key[pos] = (l << 16) | (i4 * 4 + c); }
                        }
                    }
                }
            }
            __syncthreads();
            bool ok = (s_cnt <= CAP) && (s_cntl[0] >= KSEL) && (s_cntl[1] >= KSEL) && (s_cntl[2] >= KSEL);
            if (ok) break;
            #pragma unroll
            for (int l = 0; l < 3; l++) {
                if (s_cntl[l] < KSEL) T[l] -= 0.75f;
                else if (s_cnt > CAP && s_cntl[l] > 4 * KSEL) T[l] += 0.5f;
            }
            __syncthreads();
        }
        total = min(s_cnt, CAP);
    }

    // sigmoid on survivors (reference tie semantics are on scores)
    for (int i = tid; i < total; i += nthr)
        s_v[i] = 1.0f / (1.0f + expf(-s_v[i]));
    __syncthreads();

    if (tid >= 32) return;
    const int lane = tid;

    // exact global top-20 (score desc, level asc, idx asc)
    for (int k = 0; k < KSEL; k++) {
        float bv = -1e30f; int bk = 0x7fffffff; int bpos = -1;
        for (int j = lane; j < total; j += 32) {
            float v = s_v[j]; int key = s_key[j];
            if (better(v, key, bv, bk)) { bv = v; bk = key; bpos = j; }
        }
        #pragma unroll
        for (int o = 16; o >= 1; o >>= 1) {
            float ov = __shfl_down_sync(0xffffffffu, bv, o);
            int   ok2 = __shfl_down_sync(0xffffffffu, bk, o);
            int   op  = __shfl_down_sync(0xffffffffu, bpos, o);
            if (better(ov, ok2, bv, bk)) { bv = ov; bk = ok2; bpos = op; }
        }
        if (lane == 0) {
            if (bpos >= 0) { sel_s[k] = bv; sel_key[k] = bk; s_v[bpos] = -1e30f; }
            else           { sel_s[k] = -1e30f; sel_key[k] = 0; }
        }
        __syncwarp();
    }

    // gather + decode 20 boxes
    if (lane < KSEL) {
        int key = sel_key[lane];
        int l = key >> 16, idx = key & 0xffff;
        int S = (l == 0) ? 32 : ((l == 1) ? 16 : 8);
        int N = S * S * S;
        float stride = 128.0f / (float)S;
        int z = idx / (S * S);
        int rem = idx - z * S * S;
        int y = rem / S;
        int x = rem - y * S;
        const float* shp = (l == 0) ? shp0 : ((l == 1) ? shp1 : shp2);
        const float* off = (l == 0) ? off0 : ((l == 1) ? off1 : off2);
        size_t base = (size_t)b * 3 * N;
        float cz = ((float)z + off[base + 0 * (size_t)N + idx]) * stride;
        float cy = ((float)y + off[base + 1 * (size_t)N + idx]) * stride;
        float cx = ((float)x + off[base + 2 * (size_t)N + idx]) * stride;
        s_box[lane][0] = cz;
        s_box[lane][1] = cy;
        s_box[lane][2] = cx;
        s_box[lane][3] = shp[base + 0 * (size_t)N + idx];
        s_box[lane][4] = shp[base + 1 * (size_t)N + idx];
        s_box[lane][5] = shp[base + 2 * (size_t)N + idx];
        float sc = sel_s[lane];
        s_score[lane] = sc;
        s_valid[lane] = (sc > 0.15f) ? 1 : 0;
    }
    __syncwarp();

    // pairwise 3D IoU (lower triangle)
    for (int p = lane; p < KSEL * KSEL; p += 32) {
        int i = p / KSEL, j = p % KSEL;
        if (j < i) {
            float inter = 1.0f, voli = 1.0f, volj = 1.0f;
            #pragma unroll
            for (int d = 0; d < 3; d++) {
                float ci = s_box[i][d],      cj = s_box[j][d];
                float si = fmaxf(s_box[i][3 + d], 0.0f);
                float sj = fmaxf(s_box[j][3 + d], 0.0f);
                float loi = ci - 0.5f * si, hii = ci + 0.5f * si;
                float loj = cj - 0.5f * sj, hij = cj + 0.5f * sj;
                float w = fminf(hii, hij) - fmaxf(loi, loj);
                inter *= fmaxf(w, 0.0f);
                voli *= si; volj *= sj;
            }
            s_iou[p] = inter / (voli + volj - inter + 1e-8f);
        }
    }
    __syncwarp();

    // greedy NMS (serial, lane 0)
    if (lane == 0) {
        unsigned kept = 0; int kc = 0;
        for (int i = 0; i < KSEL; i++) {
            bool sup = false;
            for (int j = 0; j < i; j++)
                if (((kept >> j) & 1u) && s_iou[i * KSEL + j] > 0.05f) sup = true;
            bool kp = (s_valid[i] != 0) && !sup;
            if (kp) kept |= (1u << i);
            s_rowof[i] = kp ? kc++ : -1;
        }
        s_count = kc;
    }
    __syncwarp();

    // write kept rows + fill remaining rows [count,20) with -1
    if (lane < KSEL) {
        int r = s_rowof[lane];
        if (r >= 0) {
            float* o = out + (size_t)b * ROWB + (size_t)r * 8;
            o[0] = 1.0f;
            o[1] = s_score[lane];
            o[2] = s_box[lane][0];
            o[3] = s_box[lane][1];
            o[4] = s_box[lane][2];
            o[5] = s_box[lane][3];
            o[6] = s_box[lane][4];
            o[7] = s_box[lane][5];
        }
    }
    {
        int kc = s_count;
        for (int r = kc + lane; r < KSEL; r += 32) {
            float* o = out + (size_t)b * ROWB + (size_t)r * 8;
            #pragma unroll
            for (int e = 0; e < 8; e++) o[e] = -1.0f;
        }
    }
}

extern "C" void kernel_launch(void* const* d_in, const int* in_sizes, int n_in,
                              void* d_out, int out_size) {
    const float* cls0 = (const float*)d_in[0];
    const float* shp0 = (const float*)d_in[1];
    const float* off0 = (const float*)d_in[2];
    const float* cls1 = (const float*)d_in[3];
    const float* shp1 = (const float*)d_in[4];
    const float* off1 = (const float*)d_in[5];
    const float* cls2 = (const float*)d_in[6];
    const float* shp2 = (const float*)d_in[7];
    const float* off2 = (const float*)d_in[8];
    float* out = (float*)d_out;

    init_kernel<<<BATCH, 256>>>(out);
    scan_kernel<<<dim3(8, BATCH), 256>>>(cls0, cls1, cls2);
    select_kernel<<<BATCH, 128>>>(cls0, shp0, off0, cls1, shp1, off1,
                                  cls2, shp2, off2, out);
}

// round 4
// speedup vs baseline: 1.2516x; 1.2516x over previous
#include <cuda_runtime.h>
#include <math.h>

#define KSEL   20
#define CAP    2048
#define M_OUT  180
#define ROWB   (M_OUT * 8)

__device__ __forceinline__ bool better(float va, int ka, float vb, int kb) {
    return (va > vb) || (va == vb && ka < kb);
}

// Warp-aggregated append to shared candidate buffer.
__device__ __forceinline__ void push(float v, int key, bool pred,
                                     int* s_cnt, float* s_v, int* s_key) {
    unsigned mask = __ballot_sync(0xffffffffu, pred);
    if (mask) {
        int lane   = threadIdx.x & 31;
        int leader = __ffs(mask) - 1;
        int base   = 0;
        if (lane == leader) base = atomicAdd(s_cnt, __popc(mask));
        base = __shfl_sync(0xffffffffu, base, leader);
        if (pred) {
            int pos = base + __popc(mask & ((1u << lane) - 1u));
            if (pos < CAP) { s_v[pos] = v; s_key[pos] = key; }
        }
    }
}

__global__ __launch_bounds__(512)
void detpost_kernel(const float* __restrict__ cls0, const float* __restrict__ shp0, const float* __restrict__ off0,
                    const float* __restrict__ cls1, const float* __restrict__ shp1, const float* __restrict__ off1,
                    const float* __restrict__ cls2, const float* __restrict__ shp2, const float* __restrict__ off2,
                    float* __restrict__ out)
{
    const int b   = blockIdx.x;
    const int tid = threadIdx.x;
    const int nthr = blockDim.x;   // 512

    __shared__ float s_v[CAP];
    __shared__ int   s_key[CAP];
    __shared__ int   s_cnt;
    __shared__ int   s_c0, s_c1;
    __shared__ float sel_s[KSEL];
    __shared__ int   sel_key[KSEL];
    __shared__ float s_box[KSEL][6];
    __shared__ float s_score[KSEL];
    __shared__ int   s_valid[KSEL];
    __shared__ float s_iou[KSEL * KSEL];
    __shared__ int   s_rowof[KSEL];
    __shared__ int   s_count;

    const float4* p0 = (const float4*)(cls0 + (size_t)b * 32768);
    const float4* p1 = (const float4*)(cls1 + (size_t)b * 4096);
    const float4* p2 = (const float4*)(cls2 + (size_t)b * 512);

    // ---------------- Phase 1: high-MLP threshold scan ----------------
    if (tid == 0) s_cnt = 0;
    __syncthreads();

    const float T0 = 2.5f, T1 = 1.9f, T2 = 1.0f;

    // Level 0: 8192 float4 -> 16/thread, 2 batches of 8 independent LDG.128
    #pragma unroll
    for (int batch = 0; batch < 2; batch++) {
        float4 r[8];
        #pragma unroll
        for (int u = 0; u < 8; u++)
            r[u] = p0[(batch * 8 + u) * 512 + tid];
        #pragma unroll
        for (int u = 0; u < 8; u++) {
            int idx = ((batch * 8 + u) * 512 + tid) * 4;
            push(r[u].x, idx + 0, r[u].x > T0, &s_cnt, s_v, s_key);
            push(r[u].y, idx + 1, r[u].y > T0, &s_cnt, s_v, s_key);
            push(r[u].z, idx + 2, r[u].z > T0, &s_cnt, s_v, s_key);
            push(r[u].w, idx + 3, r[u].w > T0, &s_cnt, s_v, s_key);
        }
    }
    __syncthreads();
    if (tid == 0) s_c0 = s_cnt;
    __syncthreads();

    // Level 1: 1024 float4 -> 2/thread
    {
        float4 r[2];
        #pragma unroll
        for (int u = 0; u < 2; u++)
            r[u] = p1[u * 512 + tid];
        #pragma unroll
        for (int u = 0; u < 2; u++) {
            int idx = (u * 512 + tid) * 4;
            int key = (1 << 16) | idx;
            push(r[u].x, key + 0, r[u].x > T1, &s_cnt, s_v, s_key);
            push(r[u].y, key + 1, r[u].y > T1, &s_cnt, s_v, s_key);
            push(r[u].z, key + 2, r[u].z > T1, &s_cnt, s_v, s_key);
            push(r[u].w, key + 3, r[u].w > T1, &s_cnt, s_v, s_key);
        }
    }
    __syncthreads();
    if (tid == 0) s_c1 = s_cnt;
    __syncthreads();

    // Level 2: 128 float4 -> warps 0..3 only (uniform per warp)
    if (tid < 128) {
        float4 r = p2[tid];
        int idx = tid * 4;
        int key = (2 << 16) | idx;
        push(r.x, key + 0, r.x > T2, &s_cnt, s_v, s_key);
        push(r.y, key + 1, r.y > T2, &s_cnt, s_v, s_key);
        push(r.z, key + 2, r.z > T2, &s_cnt, s_v, s_key);
        push(r.w, key + 3, r.w > T2, &s_cnt, s_v, s_key);
    }
    __syncthreads();

    int total = s_cnt;
    int c0 = s_c0, c1 = s_c1 - s_c0, c2 = s_cnt - s_c1;
    bool hot = (total <= CAP) && (c0 >= KSEL) && (c1 >= KSEL) && (c2 >= KSEL);

    if (!hot) {
        // Cold fallback (statistically unreachable): adaptive-threshold rescan.
        const float* clsp[3] = {cls0, cls1, cls2};
        const int    Ns[3]   = {32768, 4096, 512};
        float T[3] = {2.5f, 1.9f, 1.0f};
        __shared__ int s_cntl[3];
        for (int attempt = 0; attempt < 32; attempt++) {
            if (tid == 0) { s_cnt = 0; s_cntl[0] = 0; s_cntl[1] = 0; s_cntl[2] = 0; }
            __syncthreads();
            #pragma unroll
            for (int l = 0; l < 3; l++) {
                const int N = Ns[l];
                const float4* p = (const float4*)(clsp[l] + (size_t)b * N);
                const float Tl = T[l];
                for (int i4 = tid; i4 < (N >> 2); i4 += nthr) {
                    float4 v = p[i4];
                    float vv[4] = {v.x, v.y, v.z, v.w};
                    #pragma unroll
                    for (int c = 0; c < 4; c++) {
                        if (vv[c] > Tl) {
                            atomicAdd(&s_cntl[l], 1);
                            int pos = atomicAdd(&s_cnt, 1);
                            if (pos < CAP) { s_v[pos] = vv[c]; s_key[pos] = (l << 16) | (i4 * 4 + c); }
                        }
                    }
                }
            }
            __syncthreads();
            bool ok = (s_cnt <= CAP) && (s_cntl[0] >= KSEL) && (s_cntl[1] >= KSEL) && (s_cntl[2] >= KSEL);
            if (ok) break;
            #pragma unroll
            for (int l = 0; l < 3; l++) {
                if (s_cntl[l] < KSEL) T[l] -= 0.75f;
                else if (s_cnt > CAP && s_cntl[l] > 4 * KSEL) T[l] += 0.5f;
            }
            __syncthreads();
        }
        total = min(s_cnt, CAP);
    }

    // sigmoid on survivors (reference tie semantics live on scores)
    for (int i = tid; i < total; i += nthr)
        s_v[i] = 1.0f / (1.0f + expf(-s_v[i]));
    __syncthreads();

    // ---- Warps 1..15: fill rows 20..179 with -1 (disjoint writes) ----
    if (tid >= 32) {
        float4* o4 = (float4*)(out + (size_t)b * ROWB + KSEL * 8);
        const float4 neg = make_float4(-1.f, -1.f, -1.f, -1.f);
        for (int e = tid - 32; e < (M_OUT - KSEL) * 2; e += nthr - 32)
            o4[e] = neg;
        return;
    }

    // ---- Warp 0: exact global top-20 (score desc, level asc, idx asc) ----
    const int lane = tid;
    for (int k = 0; k < KSEL; k++) {
        float bv = -1e30f; int bk = 0x7fffffff; int bpos = -1;
        for (int j = lane; j < total; j += 32) {
            float v = s_v[j]; int key = s_key[j];
            if (better(v, key, bv, bk)) { bv = v; bk = key; bpos = j; }
        }
        #pragma unroll
        for (int o = 16; o >= 1; o >>= 1) {
            float ov  = __shfl_down_sync(0xffffffffu, bv, o);
            int   ok2 = __shfl_down_sync(0xffffffffu, bk, o);
            int   op  = __shfl_down_sync(0xffffffffu, bpos, o);
            if (better(ov, ok2, bv, bk)) { bv = ov; bk = ok2; bpos = op; }
        }
        if (lane == 0) {
            if (bpos >= 0) { sel_s[k] = bv; sel_key[k] = bk; s_v[bpos] = -1e30f; }
            else           { sel_s[k] = -1e30f; sel_key[k] = 0; }
        }
        __syncwarp();
    }

    // ---- Gather + decode 20 boxes ----
    if (lane < KSEL) {
        int key = sel_key[lane];
        int l = key >> 16, idx = key & 0xffff;
        int S = (l == 0) ? 32 : ((l == 1) ? 16 : 8);
        int N = S * S * S;
        float stride = 128.0f / (float)S;
        int z = idx / (S * S);
        int rem = idx - z * S * S;
        int y = rem / S;
        int x = rem - y * S;
        const float* shp = (l == 0) ? shp0 : ((l == 1) ? shp1 : shp2);
        const float* off = (l == 0) ? off0 : ((l == 1) ? off1 : off2);
        size_t base = (size_t)b * 3 * N;
        float cz = ((float)z + off[base + 0 * (size_t)N + idx]) * stride;
        float cy = ((float)y + off[base + 1 * (size_t)N + idx]) * stride;
        float cx = ((float)x + off[base + 2 * (size_t)N + idx]) * stride;
        s_box[lane][0] = cz;
        s_box[lane][1] = cy;
        s_box[lane][2] = cx;
        s_box[lane][3] = shp[base + 0 * (size_t)N + idx];
        s_box[lane][4] = shp[base + 1 * (size_t)N + idx];
        s_box[lane][5] = shp[base + 2 * (size_t)N + idx];
        float sc = sel_s[lane];
        s_score[lane] = sc;
        s_valid[lane] = (sc > 0.15f) ? 1 : 0;
    }
    __syncwarp();

    // ---- Pairwise 3D IoU (lower triangle) ----
    for (int p = lane; p < KSEL * KSEL; p += 32) {
        int i = p / KSEL, j = p % KSEL;
        if (j < i) {
            float inter = 1.0f, voli = 1.0f, volj = 1.0f;
            #pragma unroll
            for (int d = 0; d < 3; d++) {
                float ci = s_box[i][d],      cj = s_box[j][d];
                float si = fmaxf(s_box[i][3 + d], 0.0f);
                float sj = fmaxf(s_box[j][3 + d], 0.0f);
                float loi = ci - 0.5f * si, hii = ci + 0.5f * si;
                float loj = cj - 0.5f * sj, hij = cj + 0.5f * sj;
                float w = fminf(hii, hij) - fmaxf(loi, loj);
                inter *= fmaxf(w, 0.0f);
                voli *= si; volj *= sj;
            }
            s_iou[p] = inter / (voli + volj - inter + 1e-8f);
        }
    }
    __syncwarp();

    // ---- Greedy NMS (serial, lane 0) ----
    if (lane == 0) {
        unsigned kept = 0; int kc = 0;
        for (int i = 0; i < KSEL; i++) {
            bool sup = false;
            for (int j = 0; j < i; j++)
                if (((kept >> j) & 1u) && s_iou[i * KSEL + j] > 0.05f) sup = true;
            bool kp = (s_valid[i] != 0) && !sup;
            if (kp) kept |= (1u << i);
            s_rowof[i] = kp ? kc++ : -1;
        }
        s_count = kc;
    }
    __syncwarp();

    // ---- Write kept rows + fill remaining rows [count,20) ----
    if (lane < KSEL) {
        int r = s_rowof[lane];
        if (r >= 0) {
            float* o = out + (size_t)b * ROWB + (size_t)r * 8;
            o[0] = 1.0f;
            o[1] = s_score[lane];
            o[2] = s_box[lane][0];
            o[3] = s_box[lane][1];
            o[4] = s_box[lane][2];
            o[5] = s_box[lane][3];
            o[6] = s_box[lane][4];
            o[7] = s_box[lane][5];
        }
    }
    {
        int kc = s_count;
        for (int r = kc + lane; r < KSEL; r += 32) {
            float4* o = (float4*)(out + (size_t)b * ROWB + (size_t)r * 8);
            const float4 neg = make_float4(-1.f, -1.f, -1.f, -1.f);
            o[0] = neg; o[1] = neg;
        }
    }
}

extern "C" void kernel_launch(void* const* d_in, const int* in_sizes, int n_in,
                              void* d_out, int out_size) {
    detpost_kernel<<<64, 512>>>(
        (const float*)d_in[0], (const float*)d_in[1], (const float*)d_in[2],
        (const float*)d_in[3], (const float*)d_in[4], (const float*)d_in[5],
        (const float*)d_in[6], (const float*)d_in[7], (const float*)d_in[8],
        (float*)d_out);
}

// round 5
// speedup vs baseline: 2.0156x; 1.6104x over previous
#include <cuda_runtime.h>
#include <math.h>

#define KSEL   20
#define POOL   2048
#define M_OUT  180
#define ROWB   (M_OUT * 8)
#define KMAX   262143u   // 2^18 - 1

// Pack survivor into monotone sort key: higher score first, then smaller (level,idx).
// Invalid (score <= 0.15) gets score-bits 0 -> sorts after all valid, by key asc
// (matches reference -inf tie semantics).
__device__ __forceinline__ unsigned long long mkpack(float logit, int key) {
    float sc = 1.0f / (1.0f + expf(-logit));
    unsigned sb = (sc > 0.15f) ? __float_as_uint(sc) : 0u;
    return ((unsigned long long)sb << 18) | (unsigned long long)(KMAX - (unsigned)key);
}

// Warp-aggregated append (convergent call).
__device__ __forceinline__ void push1(float v, int key, bool pred,
                                      int* s_cnt, unsigned long long* sp) {
    unsigned mask = __ballot_sync(0xffffffffu, pred);
    if (mask) {
        int lane   = threadIdx.x & 31;
        int leader = __ffs(mask) - 1;
        int base = 0;
        if (lane == leader) base = atomicAdd(s_cnt, __popc(mask));
        base = __shfl_sync(0xffffffffu, base, leader);
        if (pred) {
            int pos = base + __popc(mask & ((1u << lane) - 1u));
            if (pos < POOL) sp[pos] = mkpack(v, key);
        }
    }
}

// Fast-path: one ballot per float4; detailed pushes only if any lane hit.
__device__ __forceinline__ void push4(float4 v, int key, float T,
                                      int* s_cnt, unsigned long long* sp) {
    float m = fmaxf(fmaxf(v.x, v.y), fmaxf(v.z, v.w));
    if (__any_sync(0xffffffffu, m > T)) {
        push1(v.x, key + 0, v.x > T, s_cnt, sp);
        push1(v.y, key + 1, v.y > T, s_cnt, sp);
        push1(v.z, key + 2, v.z > T, s_cnt, sp);
        push1(v.w, key + 3, v.w > T, s_cnt, sp);
    }
}

__global__ __launch_bounds__(512)
void detpost_kernel(const float* __restrict__ cls0, const float* __restrict__ shp0, const float* __restrict__ off0,
                    const float* __restrict__ cls1, const float* __restrict__ shp1, const float* __restrict__ off1,
                    const float* __restrict__ cls2, const float* __restrict__ shp2, const float* __restrict__ off2,
                    float* __restrict__ out)
{
    const int b   = blockIdx.x;
    const int tid = threadIdx.x;

    __shared__ unsigned long long sp[POOL];
    __shared__ int   s_cnt;
    __shared__ int   s_c0, s_c01;
    __shared__ unsigned long long s_selp[KSEL];
    __shared__ float s_box[KSEL][6];
    __shared__ float s_score[KSEL];
    __shared__ int   s_valid[KSEL];
    __shared__ float s_iou[KSEL * KSEL];
    __shared__ int   s_rowof[KSEL];
    __shared__ int   s_count;

    const float4* p0 = (const float4*)(cls0 + (size_t)b * 32768);
    const float4* p1 = (const float4*)(cls1 + (size_t)b * 4096);
    const float4* p2 = (const float4*)(cls2 + (size_t)b * 512);

    // ---------------- Phase 1: threshold scan (high MLP, cheap predicate) ----------------
    if (tid == 0) s_cnt = 0;
    if (tid < KSEL) s_selp[tid] = 0ull;
    __syncthreads();

    const float T0 = 2.90f, T1 = 2.25f, T2 = 1.30f;

    // Level 0: 8192 float4 -> 16/thread, 2 batches of 8 independent LDG.128
    #pragma unroll
    for (int batch = 0; batch < 2; batch++) {
        float4 r[8];
        #pragma unroll
        for (int u = 0; u < 8; u++)
            r[u] = p0[(batch * 8 + u) * 512 + tid];
        #pragma unroll
        for (int u = 0; u < 8; u++) {
            int key = ((batch * 8 + u) * 512 + tid) * 4;
            push4(r[u], key, T0, &s_cnt, sp);
        }
    }
    __syncthreads();
    if (tid == 0) s_c0 = s_cnt;
    __syncthreads();

    // Level 1: 1024 float4 -> 2/thread
    {
        float4 r0 = p1[tid];
        float4 r1 = p1[512 + tid];
        push4(r0, (1 << 16) | (tid * 4),         T1, &s_cnt, sp);
        push4(r1, (1 << 16) | ((512 + tid) * 4), T1, &s_cnt, sp);
    }
    __syncthreads();
    if (tid == 0) s_c01 = s_cnt;
    __syncthreads();

    // Level 2: 128 float4 -> warps 0..3
    if (tid < 128) {
        float4 r = p2[tid];
        push4(r, (2 << 16) | (tid * 4), T2, &s_cnt, sp);
    }
    __syncthreads();

    int total = s_cnt;
    int c0 = s_c0, c1 = s_c01 - s_c0, c2 = total - s_c01;
    bool hot = (total <= POOL) && (c0 >= KSEL) && (c1 >= KSEL) && (c2 >= KSEL);

    if (!hot) {
        // Cold fallback (statistically unreachable): adaptive-threshold rescan.
        float T[3] = {T0, T1, T2};
        const float4* ps[3] = {p0, p1, p2};
        const int nf4[3] = {8192, 1024, 128};
        __shared__ int s_snap[3];
        for (int attempt = 0; attempt < 32; attempt++) {
            if (tid == 0) s_cnt = 0;
            __syncthreads();
            #pragma unroll
            for (int l = 0; l < 3; l++) {
                for (int i4 = tid; i4 < nf4[l]; i4 += 512) {
                    float4 v = ps[l][i4];
                    push4(v, (l << 16) | (i4 * 4), T[l], &s_cnt, sp);
                }
                __syncthreads();
                if (tid == 0) s_snap[l] = s_cnt;
                __syncthreads();
            }
            int cc[3];
            cc[0] = s_snap[0]; cc[1] = s_snap[1] - s_snap[0]; cc[2] = s_snap[2] - s_snap[1];
            total = s_snap[2];
            bool ok = (total <= POOL) && (cc[0] >= KSEL) && (cc[1] >= KSEL) && (cc[2] >= KSEL);
            if (ok) break;
            #pragma unroll
            for (int l = 0; l < 3; l++) {
                if (cc[l] < KSEL) T[l] = fmaxf(T[l] - 0.75f, -1.7f);
                else if (total > POOL && cc[l] > 4 * KSEL) T[l] += 0.5f;
            }
            __syncthreads();
        }
        total = min(total, POOL);
    }

    // ---------------- Phase 2: parallel rank-select (exact top-20, sorted) ----------------
    for (int t = tid; t < total; t += 512) {
        unsigned long long p = sp[t];
        int r = 0, j = 0;
        for (; j + 4 <= total; j += 4) {
            r += (sp[j]   > p);
            r += (sp[j+1] > p);
            r += (sp[j+2] > p);
            r += (sp[j+3] > p);
        }
        for (; j < total; j++) r += (sp[j] > p);
        if (r < KSEL) s_selp[r] = p;
    }
    __syncthreads();

    // ---- Warps 1..15: fill rows 20..179 with -1 (disjoint writes) ----
    if (tid >= 32) {
        float4* o4 = (float4*)(out + (size_t)b * ROWB + KSEL * 8);
        const float4 neg = make_float4(-1.f, -1.f, -1.f, -1.f);
        for (int e = tid - 32; e < (M_OUT - KSEL) * 2; e += 480)
            o4[e] = neg;
        return;
    }

    const int lane = tid;

    // ---- Decode the 20 selected candidates ----
    if (lane < KSEL) {
        unsigned long long p = s_selp[lane];
        float sc = __uint_as_float((unsigned)(p >> 18));
        int key = (int)(KMAX - (unsigned)(p & (unsigned long long)KMAX));
        int l = key >> 16, idx = key & 0xffff;
        bool haveBox = (p != 0ull) && (l <= 2);
        float bz = 0.f, by = 0.f, bx = 0.f, d0 = 0.f, d1 = 0.f, d2 = 0.f;
        if (haveBox) {
            int S = (l == 0) ? 32 : ((l == 1) ? 16 : 8);
            int N = S * S * S;
            float stride = 128.0f / (float)S;
            int z = idx / (S * S);
            int rem = idx - z * S * S;
            int y = rem / S;
            int x = rem - y * S;
            const float* shp = (l == 0) ? shp0 : ((l == 1) ? shp1 : shp2);
            const float* off = (l == 0) ? off0 : ((l == 1) ? off1 : off2);
            size_t base = (size_t)b * 3 * N;
            bz = ((float)z + off[base + 0 * (size_t)N + idx]) * stride;
            by = ((float)y + off[base + 1 * (size_t)N + idx]) * stride;
            bx = ((float)x + off[base + 2 * (size_t)N + idx]) * stride;
            d0 = shp[base + 0 * (size_t)N + idx];
            d1 = shp[base + 1 * (size_t)N + idx];
            d2 = shp[base + 2 * (size_t)N + idx];
        }
        s_box[lane][0] = bz; s_box[lane][1] = by; s_box[lane][2] = bx;
        s_box[lane][3] = d0; s_box[lane][4] = d1; s_box[lane][5] = d2;
        s_score[lane] = sc;
        s_valid[lane] = ((p >> 18) != 0ull) ? 1 : 0;
    }
    __syncwarp();

    // ---- Pairwise 3D IoU (lower triangle) ----
    for (int p = lane; p < KSEL * KSEL; p += 32) {
        int i = p / KSEL, j = p % KSEL;
        if (j < i) {
            float inter = 1.0f, voli = 1.0f, volj = 1.0f;
            #pragma unroll
            for (int d = 0; d < 3; d++) {
                float ci = s_box[i][d],      cj = s_box[j][d];
                float si = fmaxf(s_box[i][3 + d], 0.0f);
                float sj = fmaxf(s_box[j][3 + d], 0.0f);
                float loi = ci - 0.5f * si, hii = ci + 0.5f * si;
                float loj = cj - 0.5f * sj, hij = cj + 0.5f * sj;
                float w = fminf(hii, hij) - fmaxf(loi, loj);
                inter *= fmaxf(w, 0.0f);
                voli *= si; volj *= sj;
            }
            s_iou[p] = inter / (voli + volj - inter + 1e-8f);
        }
    }
    __syncwarp();

    // ---- Greedy NMS (serial, lane 0) ----
    if (lane == 0) {
        unsigned kept = 0; int kc = 0;
        for (int i = 0; i < KSEL; i++) {
            bool sup = false;
            for (int j = 0; j < i; j++)
                if (((kept >> j) & 1u) && s_iou[i * KSEL + j] > 0.05f) sup = true;
            bool kp = (s_valid[i] != 0) && !sup;
            if (kp) kept |= (1u << i);
            s_rowof[i] = kp ? kc++ : -1;
        }
        s_count = kc;
    }
    __syncwarp();

    // ---- Write kept rows + fill rows [count,20) with -1 ----
    if (lane < KSEL) {
        int r = s_rowof[lane];
        if (r >= 0) {
            float4* o4 = (float4*)(out + (size_t)b * ROWB + (size_t)r * 8);
            o4[0] = make_float4(1.0f, s_score[lane], s_box[lane][0], s_box[lane][1]);
            o4[1] = make_float4(s_box[lane][2], s_box[lane][3], s_box[lane][4], s_box[lane][5]);
        }
    }
    {
        int kc = s_count;
        const float4 neg = make_float4(-1.f, -1.f, -1.f, -1.f);
        for (int r = kc + lane; r < KSEL; r += 32) {
            float4* o4 = (float4*)(out + (size_t)b * ROWB + (size_t)r * 8);
            o4[0] = neg; o4[1] = neg;
        }
    }
}

extern "C" void kernel_launch(void* const* d_in, const int* in_sizes, int n_in,
                              void* d_out, int out_size) {
    detpost_kernel<<<64, 512>>>(
        (const float*)d_in[0], (const float*)d_in[1], (const float*)d_in[2],
        (const float*)d_in[3], (const float*)d_in[4], (const float*)d_in[5],
        (const float*)d_in[6], (const float*)d_in[7], (const float*)d_in[8],
        (float*)d_out);
}

// round 6
// speedup vs baseline: 2.3409x; 1.1614x over previous
#include <cuda_runtime.h>
#include <math.h>

#define KSEL   20
#define SEG    640
#define POOL   1280
#define M_OUT  180
#define ROWB   (M_OUT * 8)
#define KMAX   262143u   // 2^18 - 1
#define NMS_TH 0.05f

__device__ __forceinline__ unsigned smem_u32(const void* p) {
    return (unsigned)__cvta_generic_to_shared(p);
}
__device__ __forceinline__ unsigned mapa0(unsigned addr) {
    unsigned r;
    asm("mapa.shared::cluster.u32 %0, %1, %2;" : "=r"(r) : "r"(addr), "r"(0));
    return r;
}
__device__ __forceinline__ unsigned my_ctarank() {
    unsigned r; asm("mov.u32 %0, %%cluster_ctarank;" : "=r"(r)); return r;
}

// Pack survivor: higher score first, then smaller (level,idx). Invalid (<=0.15) -> score bits 0.
__device__ __forceinline__ unsigned long long mkpack(float logit, int key) {
    float sc = 1.0f / (1.0f + expf(-logit));
    unsigned sb = (sc > 0.15f) ? __float_as_uint(sc) : 0u;
    return ((unsigned long long)sb << 18) | (unsigned long long)(KMAX - (unsigned)key);
}

// ---- local push (rank 0 / cold path): warp-aggregated into own smem pool ----
__device__ __forceinline__ void push1_l(float v, int key, bool pred,
                                        int* cnt, unsigned long long* pool, int cap) {
    unsigned mask = __ballot_sync(0xffffffffu, pred);
    if (mask) {
        int lane = threadIdx.x & 31;
        int leader = __ffs(mask) - 1;
        int base = 0;
        if (lane == leader) base = atomicAdd(cnt, __popc(mask));
        base = __shfl_sync(0xffffffffu, base, leader);
        if (pred) {
            int pos = base + __popc(mask & ((1u << lane) - 1u));
            if (pos < cap) pool[pos] = mkpack(v, key);
        }
    }
}
__device__ __forceinline__ void push4_l(float4 v, int key, float T,
                                        int* cnt, unsigned long long* pool, int cap) {
    float m = fmaxf(fmaxf(v.x, v.y), fmaxf(v.z, v.w));
    if (__any_sync(0xffffffffu, m > T)) {
        push1_l(v.x, key + 0, v.x > T, cnt, pool, cap);
        push1_l(v.y, key + 1, v.y > T, cnt, pool, cap);
        push1_l(v.z, key + 2, v.z > T, cnt, pool, cap);
        push1_l(v.w, key + 3, v.w > T, cnt, pool, cap);
    }
}

// ---- remote push (rank 1): local counter, store entry into rank0's segment ----
__device__ __forceinline__ void push1_r(float v, int key, bool pred,
                                        int* cnt, unsigned rpool) {
    unsigned mask = __ballot_sync(0xffffffffu, pred);
    if (mask) {
        int lane = threadIdx.x & 31;
        int leader = __ffs(mask) - 1;
        int base = 0;
        if (lane == leader) base = atomicAdd(cnt, __popc(mask));
        base = __shfl_sync(0xffffffffu, base, leader);
        if (pred) {
            int pos = base + __popc(mask & ((1u << lane) - 1u));
            if (pos < SEG) {
                unsigned long long pk = mkpack(v, key);
                asm volatile("st.relaxed.cluster.shared::cluster.u64 [%0], %1;"
                             :: "r"(rpool + (unsigned)pos * 8u), "l"(pk) : "memory");
            }
        }
    }
}
__device__ __forceinline__ void push4_r(float4 v, int key, float T,
                                        int* cnt, unsigned rpool) {
    float m = fmaxf(fmaxf(v.x, v.y), fmaxf(v.z, v.w));
    if (__any_sync(0xffffffffu, m > T)) {
        push1_r(v.x, key + 0, v.x > T, cnt, rpool);
        push1_r(v.y, key + 1, v.y > T, cnt, rpool);
        push1_r(v.z, key + 2, v.z > T, cnt, rpool);
        push1_r(v.w, key + 3, v.w > T, cnt, rpool);
    }
}

__global__ __launch_bounds__(512) __cluster_dims__(2, 1, 1)
void detpost_kernel(const float* __restrict__ cls0, const float* __restrict__ shp0, const float* __restrict__ off0,
                    const float* __restrict__ cls1, const float* __restrict__ shp1, const float* __restrict__ off1,
                    const float* __restrict__ cls2, const float* __restrict__ shp2, const float* __restrict__ off2,
                    float* __restrict__ out)
{
    const int b    = blockIdx.x >> 1;
    const unsigned rank = my_ctarank();
    const int tid  = threadIdx.x;

    __shared__ unsigned long long sp[POOL];   // rank0: [0,SEG) own, [SEG,2*SEG) from rank1
    __shared__ int s_cnt;                     // this CTA's local push counter
    __shared__ int s_rtot;                    // rank0 only: rank1's count (remote-written)
    __shared__ int s_clvl[3];
    __shared__ unsigned long long s_selp[KSEL];

    const float4* p0 = (const float4*)(cls0 + (size_t)b * 32768);
    const float4* p1 = (const float4*)(cls1 + (size_t)b * 4096);
    const float4* p2 = (const float4*)(cls2 + (size_t)b * 512);

    if (tid == 0) s_cnt = 0;
    if (tid < KSEL) s_selp[tid] = 0ull;
    __syncthreads();

    const float T0 = 2.90f, T1 = 2.25f, T2 = 1.30f;

    // ---------------- Phase 1: split scan ----------------
    if (rank == 0) {
        // L0 first half: 4096 float4, 8/thread
        float4 r[8];
        #pragma unroll
        for (int u = 0; u < 8; u++) r[u] = p0[u * 512 + tid];
        #pragma unroll
        for (int u = 0; u < 8; u++)
            push4_l(r[u], (u * 512 + tid) * 4, T0, &s_cnt, sp, SEG);
    } else {
        const unsigned rpool = mapa0(smem_u32(&sp[SEG]));
        // L0 second half
        float4 r[8];
        #pragma unroll
        for (int u = 0; u < 8; u++) r[u] = p0[4096 + u * 512 + tid];
        #pragma unroll
        for (int u = 0; u < 8; u++)
            push4_r(r[u], (4096 + u * 512 + tid) * 4, T0, &s_cnt, rpool);
        // L1 (all)
        float4 q0 = p1[tid];
        float4 q1 = p1[512 + tid];
        push4_r(q0, (1 << 16) | (tid * 4),         T1, &s_cnt, rpool);
        push4_r(q1, (1 << 16) | ((512 + tid) * 4), T1, &s_cnt, rpool);
        // L2 (all) -- warps 0..3, converged per warp
        if (tid < 128) {
            float4 q2 = p2[tid];
            push4_r(q2, (2 << 16) | (tid * 4), T2, &s_cnt, rpool);
        }
    }
    __syncthreads();
    if (rank == 1 && tid == 0) {
        unsigned raddr = mapa0(smem_u32(&s_rtot));
        asm volatile("st.relaxed.cluster.shared::cluster.u32 [%0], %1;"
                     :: "r"(raddr), "r"(s_cnt) : "memory");
    }
    asm volatile("barrier.cluster.arrive.aligned;" ::: "memory");
    asm volatile("barrier.cluster.wait.aligned;"   ::: "memory");

    // ---------------- Rank 1: static -1 fill for rows 20..179, then done ----------------
    if (rank == 1) {
        float4* o4 = (float4*)(out + (size_t)b * ROWB + KSEL * 8);
        const float4 neg = make_float4(-1.f, -1.f, -1.f, -1.f);
        for (int e = tid; e < (M_OUT - KSEL) * 2; e += 512)
            o4[e] = neg;
        return;
    }

    // ---------------- Rank 0: combine, hot-check, select ----------------
    int tot0 = s_cnt;
    int tot1 = s_rtot;
    int n0 = min(tot0, SEG), n1 = min(tot1, SEG);

    // compact rank1 segment down to [n0, n0+n1)
    unsigned long long t0v = 0, t1v = 0;
    if (tid < n1)        t0v = sp[SEG + tid];
    if (tid + 512 < n1)  t1v = sp[SEG + tid + 512];
    if (tid < 3) s_clvl[tid] = 0;
    __syncthreads();
    if (tid < n1)        sp[n0 + tid]       = t0v;
    if (tid + 512 < n1)  sp[n0 + tid + 512] = t1v;
    __syncthreads();

    int total = n0 + n1;
    for (int t = tid; t < total; t += 512) {
        int key = (int)(KMAX - (unsigned)(sp[t] & (unsigned long long)KMAX));
        atomicAdd(&s_clvl[key >> 16], 1);
    }
    __syncthreads();

    bool hot = (tot0 <= SEG) && (tot1 <= SEG) &&
               (s_clvl[0] >= KSEL) && (s_clvl[1] >= KSEL) && (s_clvl[2] >= KSEL);

    if (!hot) {
        // Cold fallback: solo adaptive full rescan (statistically unreachable).
        float T[3] = {T0, T1, T2};
        const float4* ps[3] = {p0, p1, p2};
        const int nf4[3] = {8192, 1024, 128};
        __shared__ int s_snap[3];
        for (int attempt = 0; attempt < 32; attempt++) {
            if (tid == 0) s_cnt = 0;
            __syncthreads();
            #pragma unroll
            for (int l = 0; l < 3; l++) {
                for (int i4 = tid; i4 < nf4[l]; i4 += 512) {
                    float4 v = ps[l][i4];
                    push4_l(v, (l << 16) | (i4 * 4), T[l], &s_cnt, sp, POOL);
                }
                __syncthreads();
                if (tid == 0) s_snap[l] = s_cnt;
                __syncthreads();
            }
            int cc[3];
            cc[0] = s_snap[0]; cc[1] = s_snap[1] - s_snap[0]; cc[2] = s_snap[2] - s_snap[1];
            total = s_snap[2];
            bool ok = (total <= POOL) && (cc[0] >= KSEL) && (cc[1] >= KSEL) && (cc[2] >= KSEL);
            if (ok) break;
            #pragma unroll
            for (int l = 0; l < 3; l++) {
                if (cc[l] < KSEL) T[l] = fmaxf(T[l] - 0.75f, -1.7f);
                else if (total > POOL && cc[l] > 4 * KSEL) T[l] += 0.5f;
            }
            __syncthreads();
        }
        total = min(total, POOL);
    }

    // ---------------- Phase 2: parallel rank-select (exact top-20, sorted) ----------------
    for (int t = tid; t < total; t += 512) {
        unsigned long long p = sp[t];
        int r = 0, j = 0;
        for (; j + 4 <= total; j += 4) {
            r += (sp[j]   > p);
            r += (sp[j+1] > p);
            r += (sp[j+2] > p);
            r += (sp[j+3] > p);
        }
        for (; j < total; j++) r += (sp[j] > p);
        if (r < KSEL) s_selp[r] = p;
    }
    __syncthreads();

    if (tid >= 32) return;
    const int lane = tid;

    // ---------------- Phase 3: decode 20 candidates into lane registers ----------------
    float sc = 0.f, cz = 0.f, cy = 0.f, cx = 0.f, d0 = 0.f, d1 = 0.f, d2 = 0.f;
    int myvalid = 0;
    if (lane < KSEL) {
        unsigned long long p = s_selp[lane];
        sc = __uint_as_float((unsigned)(p >> 18));
        int key = (int)(KMAX - (unsigned)(p & (unsigned long long)KMAX));
        int l = key >> 16, idx = key & 0xffff;
        myvalid = ((p >> 18) != 0ull) ? 1 : 0;
        if (p != 0ull && l <= 2) {
            int S = (l == 0) ? 32 : ((l == 1) ? 16 : 8);
            int N = S * S * S;
            float stride = 128.0f / (float)S;
            int z = idx / (S * S);
            int rem = idx - z * S * S;
            int y = rem / S;
            int x = rem - y * S;
            const float* shp = (l == 0) ? shp0 : ((l == 1) ? shp1 : shp2);
            const float* off = (l == 0) ? off0 : ((l == 1) ? off1 : off2);
            size_t base = (size_t)b * 3 * N;
            cz = ((float)z + off[base + 0 * (size_t)N + idx]) * stride;
            cy = ((float)y + off[base + 1 * (size_t)N + idx]) * stride;
            cx = ((float)x + off[base + 2 * (size_t)N + idx]) * stride;
            d0 = shp[base + 0 * (size_t)N + idx];
            d1 = shp[base + 1 * (size_t)N + idx];
            d2 = shp[base + 2 * (size_t)N + idx];
        }
    }

    // per-lane clamped extents + volume
    float sz0 = fmaxf(d0, 0.f), sz1 = fmaxf(d1, 0.f), sz2 = fmaxf(d2, 0.f);
    float lz = cz - 0.5f * sz0, hz = cz + 0.5f * sz0;
    float ly = cy - 0.5f * sz1, hy = cy + 0.5f * sz1;
    float lx = cx - 0.5f * sz2, hx = cx + 0.5f * sz2;
    float vol = sz0 * sz1 * sz2;

    // ---------------- Phase 4: warp-parallel greedy NMS ----------------
    unsigned keptmask = 0;
    #pragma unroll
    for (int i = 0; i < KSEL; i++) {
        float liz = __shfl_sync(0xffffffffu, lz, i);
        float liy = __shfl_sync(0xffffffffu, ly, i);
        float lix = __shfl_sync(0xffffffffu, lx, i);
        float hiz = __shfl_sync(0xffffffffu, hz, i);
        float hiy = __shfl_sync(0xffffffffu, hy, i);
        float hix = __shfl_sync(0xffffffffu, hx, i);
        float voi = __shfl_sync(0xffffffffu, vol, i);
        int   vi  = __shfl_sync(0xffffffffu, myvalid, i);
        float iz = fminf(hz, hiz) - fmaxf(lz, liz);
        float iy = fminf(hy, hiy) - fmaxf(ly, liy);
        float ix = fminf(hx, hix) - fmaxf(lx, lix);
        float inter = fmaxf(iz, 0.f) * fmaxf(iy, 0.f) * fmaxf(ix, 0.f);
        float iou = inter / (voi + vol - inter + 1e-8f);
        bool p = (lane < i) && ((keptmask >> lane) & 1u) && (iou > NMS_TH);
        unsigned anyp = __ballot_sync(0xffffffffu, p);
        bool kp = vi && (anyp == 0u);
        keptmask |= (kp ? 1u : 0u) << i;
    }

    // ---------------- Phase 5: write rows 0..19 ----------------
    if (lane < KSEL && ((keptmask >> lane) & 1u)) {
        int r = __popc(keptmask & ((1u << lane) - 1u));
        float4* o4 = (float4*)(out + (size_t)b * ROWB + (size_t)r * 8);
        o4[0] = make_float4(1.0f, sc, cz, cy);
        o4[1] = make_float4(cx, d0, d1, d2);
    }
    {
        int kc = __popc(keptmask);
        const float4 neg = make_float4(-1.f, -1.f, -1.f, -1.f);
        for (int r = kc + lane; r < KSEL; r += 32) {
            float4* o4 = (float4*)(out + (size_t)b * ROWB + (size_t)r * 8);
            o4[0] = neg; o4[1] = neg;
        }
    }
}

extern "C" void kernel_launch(void* const* d_in, const int* in_sizes, int n_in,
                              void* d_out, int out_size) {
    detpost_kernel<<<128, 512>>>(
        (const float*)d_in[0], (const float*)d_in[1], (const float*)d_in[2],
        (const float*)d_in[3], (const float*)d_in[4], (const float*)d_in[5],
        (const float*)d_in[6], (const float*)d_in[7], (const float*)d_in[8],
        (float*)d_out);
}